// round 9
// baseline (speedup 1.0000x reference)
#include <cuda_runtime.h>
#include <math.h>
#include <stdint.h>

// Problem constants
#define B_   8
#define P_   16384
#define M_   16
#define CI_  16
#define CO_  32
#define W_   17
#define OSTRIDE 288       // floats per output row in Wf (17 w-slots + residual)
#define WWM  24           // per-m stride in ww_s (2 wp-halves of 12, 16B aligned)
#define WARP_SM 400       // per-warp smem floats: ww 16*24=384 + nb 16

typedef unsigned long long ull;

// packed f32x2 (SASS FFMA2) — only reachable via PTX
#define FMA_F32X2(d, a, b, c) \
    asm("fma.rn.f32x2 %0, %1, %2, %3;" : "=l"(d) : "l"(a), "l"(b), "l"(c))
#define MUL_F32X2(d, a, b) \
    asm("mul.rn.f32x2 %0, %1, %2;" : "=l"(d) : "l"(a), "l"(b))
#define PACK_REPL_F32X2(out, s) \
    asm("mov.b64 %0, {%1, %1};" : "=l"(out) : "r"(s))
#define UNPACK_F32X2(lo, hi, in) \
    asm("mov.b64 {%0, %1}, %2;" : "=r"(lo), "=r"(hi) : "l"(in))

// smem (floats): Wf [32][288] = 9216 ; per-warp (4): ww[16][24] + nb[16] = 400
// total = 9216 + 1600 = 10816 floats = 43264 bytes

__global__ void __launch_bounds__(128, 4)
fused_conv_kernel(const float* __restrict__ in_pc,
                  const float* __restrict__ weights,
                  const float* __restrict__ bias,
                  const float* __restrict__ w_weights,
                  const float* __restrict__ weight_res,
                  const int*   __restrict__ neighbor_id,
                  float*       __restrict__ out)
{
    constexpr float SQ_CONV = 0.70710678118654752440f;
    constexpr float SQ_RES  = 0.70710678118654752440f;

    extern __shared__ float sm[];
    float* Wf = sm;                                   // [32][288]

    const int tid  = threadIdx.x;
    const int warp = tid >> 5;
    const int lane = tid & 31;

    float* ww_s = sm + 32 * OSTRIDE + warp * WARP_SM; // [16][24]
    int*   nb_s = (int*)(ww_s + 384);                 // [16]

    // ---- stage weights: Wf[o][w*16+i], col 272.. holds weight_res ----
    for (int idx = tid; idx < W_ * 512; idx += 128) {
        int w   = idx >> 9;
        int rem = idx & 511;
        int o   = rem >> 4;
        int i   = rem & 15;
        Wf[o * OSTRIDE + w * 16 + i] = weights[idx];
    }
    for (int idx = tid; idx < 512; idx += 128) {
        int o = idx >> 4, i = idx & 15;
        Wf[o * OSTRIDE + 272 + i] = weight_res[idx];
    }

    const int p = blockIdx.x * 4 + warp;

    // ---- per-warp staging: neighbor ids, masked ww (parity-split layout) ----
    if (lane < 16) {
        nb_s[lane] = neighbor_id[p * M_ + lane];
        ww_s[lane * WWM + 12 + 8] = 0.0f;     // wp1 slot8 = 0 (residual slot)
    }
    __syncwarp();
    for (int idx = lane; idx < 272; idx += 32) {
        int m = idx / 17;
        int w = idx - m * 17;
        float v = w_weights[(size_t)p * 272 + idx];
        // slot: wp = w&1 ; s = w>>1  (w=16 -> wp0 s8)
        ww_s[m * WWM + (w & 1) * 12 + (w >> 1)] = (nb_s[m] == P_) ? 0.0f : v;
    }
    __syncthreads();

    // lane = bg*16 + wp*8 + ih
    const int bg = (lane >> 4) & 1;
    const int wp = (lane >> 3) & 1;
    const int ih = lane & 7;

    // 4 batches per lane: b_j = bg + 2j
    const float* xb0 = in_pc + (size_t)(bg + 0) * P_ * CI_ + 2 * ih;
    const float* xb1 = in_pc + (size_t)(bg + 2) * P_ * CI_ + 2 * ih;
    const float* xb2 = in_pc + (size_t)(bg + 4) * P_ * CI_ + 2 * ih;
    const float* xb3 = in_pc + (size_t)(bg + 6) * P_ * CI_ + 2 * ih;

    // gacc2[s][j]: packed ch-pair accumulators. s=0..7: w=2s+wp ;
    // s=8: wp0 -> w=16 conv ; wp1 -> own-x (residual input, preserved by ww=0)
    ull gacc2[9][4];
    #pragma unroll
    for (int s = 0; s < 9; s++) {
        gacc2[s][0] = 0ull; gacc2[s][1] = 0ull;
        gacc2[s][2] = 0ull; gacc2[s][3] = 0ull;
    }
    if (wp) {
        size_t po = (size_t)p * CI_;
        gacc2[8][0] = *(const ull*)(xb0 + po);
        gacc2[8][1] = *(const ull*)(xb1 + po);
        gacc2[8][2] = *(const ull*)(xb2 + po);
        gacc2[8][3] = *(const ull*)(xb3 + po);
    }

    // ---- stage A ----
    const float* wwp = ww_s + wp * 12;
    #pragma unroll 4
    for (int m = 0; m < M_; m++) {
        int nb  = nb_s[m];
        int nbc = (nb == P_) ? 0 : nb;          // ww zeroed for pad
        size_t xo = (size_t)nbc * CI_;
        ull x0 = *(const ull*)(xb0 + xo);
        ull x1 = *(const ull*)(xb1 + xo);
        ull x2 = *(const ull*)(xb2 + xo);
        ull x3 = *(const ull*)(xb3 + xo);
        const float* wm = wwp + m * WWM;
        float4 fA = *(const float4*)(wm);
        float4 fB = *(const float4*)(wm + 4);
        float  f8 = wm[8];
        float fs[9] = {fA.x, fA.y, fA.z, fA.w, fB.x, fB.y, fB.z, fB.w, f8};
        #pragma unroll
        for (int s = 0; s < 9; s++) {
            ull f2;
            uint32_t fb = __float_as_uint(fs[s]);
            PACK_REPL_F32X2(f2, fb);
            FMA_F32X2(gacc2[s][0], f2, x0, gacc2[s][0]);
            FMA_F32X2(gacc2[s][1], f2, x1, gacc2[s][1]);
            FMA_F32X2(gacc2[s][2], f2, x2, gacc2[s][2]);
            FMA_F32X2(gacc2[s][3], f2, x3, gacc2[s][3]);
        }
    }

    // ---- stage B: oo-blocks of 4; each Wf LDS.64 feeds 4 FFMA2 ----
    const float* wfih = Wf + 2 * ih;
    const int h2 = (ih >> 2) & 1;
    const int h1 = (ih >> 1) & 1;
    const int h0 = ih & 1;
    // final ownership per og: o = og*4 + wp*2 + h2 ; b = bg + 2*(h1*2+h0)
    const int o_off = wp * 2 + h2;
    const int b_fin = bg + 2 * (h1 * 2 + h0);
    float* outb = out + ((size_t)b_fin * P_ + p) * CO_;
    const float* biasp = bias + (size_t)p * CO_;

    #pragma unroll 1
    for (int og = 0; og < 8; og++) {
        const float* wfo = wfih + og * 4 * OSTRIDE;

        float av[4][4], rv[4][4];

        #pragma unroll
        for (int oo = 0; oo < 4; oo++) {
            const float* wfoo = wfo + oo * OSTRIDE;

            ull acc2[4] = {0ull, 0ull, 0ull, 0ull};
            #pragma unroll
            for (int s = 0; s < 8; s++) {
                ull wv = *(const ull*)(wfoo + (2 * s + wp) * 16);
                FMA_F32X2(acc2[0], wv, gacc2[s][0], acc2[0]);
                FMA_F32X2(acc2[1], wv, gacc2[s][1], acc2[1]);
                FMA_F32X2(acc2[2], wv, gacc2[s][2], acc2[2]);
                FMA_F32X2(acc2[3], wv, gacc2[s][3], acc2[3]);
            }
            // slot 8: wp0 -> conv w=16 (offset 256) ; wp1 -> residual (offset 272)
            ull wv8 = *(const ull*)(wfoo + (16 + wp) * 16);
            ull rt2[4] = {0ull, 0ull, 0ull, 0ull};
            if (wp == 0) {
                FMA_F32X2(acc2[0], wv8, gacc2[8][0], acc2[0]);
                FMA_F32X2(acc2[1], wv8, gacc2[8][1], acc2[1]);
                FMA_F32X2(acc2[2], wv8, gacc2[8][2], acc2[2]);
                FMA_F32X2(acc2[3], wv8, gacc2[8][3], acc2[3]);
            } else {
                MUL_F32X2(rt2[0], wv8, gacc2[8][0]);
                MUL_F32X2(rt2[1], wv8, gacc2[8][1]);
                MUL_F32X2(rt2[2], wv8, gacc2[8][2]);
                MUL_F32X2(rt2[3], wv8, gacc2[8][3]);
            }
            #pragma unroll
            for (int j = 0; j < 4; j++) {
                uint32_t lo, hi;
                UNPACK_F32X2(lo, hi, acc2[j]);
                av[oo][j] = __uint_as_float(lo) + __uint_as_float(hi);
                UNPACK_F32X2(lo, hi, rt2[j]);
                rv[oo][j] = __uint_as_float(lo) + __uint_as_float(hi);
            }
        }

        // ---- reduce-scatter over 16 lanes (bits: wp=8, h2=4, h1=2, h0=1) ----
        // Level 0 (xor 8): keep oo = wp*2 + t
        float a3[2][4], r3[2][4];
        #pragma unroll
        for (int t = 0; t < 2; t++) {
            #pragma unroll
            for (int j = 0; j < 4; j++) {
                float ka = wp ? av[2+t][j] : av[t][j];
                float sa = wp ? av[t][j]   : av[2+t][j];
                a3[t][j] = ka + __shfl_xor_sync(0xffffffffu, sa, 8);
                float kr = wp ? rv[2+t][j] : rv[t][j];
                float sr = wp ? rv[t][j]   : rv[2+t][j];
                r3[t][j] = kr + __shfl_xor_sync(0xffffffffu, sr, 8);
            }
        }
        // Level 1 (xor 4): keep t = h2
        float a2v[4], r2v[4];
        #pragma unroll
        for (int j = 0; j < 4; j++) {
            float ka = h2 ? a3[1][j] : a3[0][j];
            float sa = h2 ? a3[0][j] : a3[1][j];
            a2v[j] = ka + __shfl_xor_sync(0xffffffffu, sa, 4);
            float kr = h2 ? r3[1][j] : r3[0][j];
            float sr = h2 ? r3[0][j] : r3[1][j];
            r2v[j] = kr + __shfl_xor_sync(0xffffffffu, sr, 4);
        }
        // Level 2 (xor 2): keep j in {h1*2, h1*2+1}
        float a1v[2], r1v[2];
        #pragma unroll
        for (int u = 0; u < 2; u++) {
            float ka = h1 ? a2v[2+u] : a2v[u];
            float sa = h1 ? a2v[u]   : a2v[2+u];
            a1v[u] = ka + __shfl_xor_sync(0xffffffffu, sa, 2);
            float kr = h1 ? r2v[2+u] : r2v[u];
            float sr = h1 ? r2v[u]   : r2v[2+u];
            r1v[u] = kr + __shfl_xor_sync(0xffffffffu, sr, 2);
        }
        // Level 3 (xor 1): keep u = h0
        float a0v, r0v;
        {
            float ka = h0 ? a1v[1] : a1v[0];
            float sa = h0 ? a1v[0] : a1v[1];
            a0v = ka + __shfl_xor_sync(0xffffffffu, sa, 1);
            float kr = h0 ? r1v[1] : r1v[0];
            float sr = h0 ? r1v[0] : r1v[1];
            r0v = kr + __shfl_xor_sync(0xffffffffu, sr, 1);
        }

        // ---- epilogue: every lane owns (o = og*4 + o_off, b = b_fin) ----
        const int o = og * 4 + o_off;
        float c = a0v + biasp[o];
        float e = (c > 0.0f) ? c : expm1f(c);
        outb[o] = e * SQ_CONV + r0v * SQ_RES;
    }
}

extern "C" void kernel_launch(void* const* d_in, const int* in_sizes, int n_in,
                              void* d_out, int out_size)
{
    const float* in_pc       = nullptr;
    const float* weights     = nullptr;
    const float* bias        = nullptr;
    const float* w_weights   = nullptr;
    const float* weight_res  = nullptr;
    const int*   neighbor_id = nullptr;

    for (int i = 0; i < n_in; i++) {
        switch (in_sizes[i]) {
            case 2097152: in_pc       = (const float*)d_in[i]; break; // (8,16384,16)
            case 8704:    weights     = (const float*)d_in[i]; break; // (17,512)
            case 524288:  bias        = (const float*)d_in[i]; break; // (16384,32)
            case 4456448: w_weights   = (const float*)d_in[i]; break; // (16384,16,17)
            case 512:     weight_res  = (const float*)d_in[i]; break; // (32,16)
            case 262144:  neighbor_id = (const int*)d_in[i];   break; // (16384,16)
            default: break;
        }
    }

    const int smem_bytes = (32 * OSTRIDE + 4 * WARP_SM) * 4; // 43264
    cudaFuncSetAttribute(fused_conv_kernel,
                         cudaFuncAttributeMaxDynamicSharedMemorySize, smem_bytes);

    fused_conv_kernel<<<P_ / 4, 128, smem_bytes>>>(
        in_pc, weights, bias, w_weights, weight_res, neighbor_id, (float*)d_out);
}

// round 10
// speedup vs baseline: 1.0500x; 1.0500x over previous
#include <cuda_runtime.h>
#include <math.h>
#include <stdint.h>

// Problem constants
#define B_   8
#define P_   16384
#define M_   16
#define CI_  16
#define CO_  32
#define W_   17
#define OSTRIDE 288       // floats per output row in Wf (17 w-slots + residual)
#define WWM  24           // per-m stride in ww_s (2 wp-halves of 12)
#define WARP_SM 400       // per-warp smem floats: ww 16*24=384 + nb 16

typedef unsigned long long ull;

// packed f32x2 (SASS FFMA2) — only reachable via PTX
#define FMA_F32X2(d, a, b, c) \
    asm("fma.rn.f32x2 %0, %1, %2, %3;" : "=l"(d) : "l"(a), "l"(b), "l"(c))
#define MUL_F32X2(d, a, b) \
    asm("mul.rn.f32x2 %0, %1, %2;" : "=l"(d) : "l"(a), "l"(b))
#define PACK_REPL_F32X2(out, s) \
    asm("mov.b64 %0, {%1, %1};" : "=l"(out) : "r"(s))
#define UNPACK_F32X2(lo, hi, in) \
    asm("mov.b64 {%0, %1}, %2;" : "=r"(lo), "=r"(hi) : "l"(in))

// smem (floats): Wf [32][288] = 9216 ; per-warp (4): ww[16][24] + nb[16] = 400
// total = 9216 + 1600 = 10816 floats = 43264 bytes

__global__ void __launch_bounds__(128, 4)
fused_conv_kernel(const float* __restrict__ in_pc,
                  const float* __restrict__ weights,
                  const float* __restrict__ bias,
                  const float* __restrict__ w_weights,
                  const float* __restrict__ weight_res,
                  const int*   __restrict__ neighbor_id,
                  float*       __restrict__ out)
{
    constexpr float SQ_CONV = 0.70710678118654752440f;
    constexpr float SQ_RES  = 0.70710678118654752440f;

    extern __shared__ float sm[];
    float* Wf = sm;                                   // [32][288]

    const int tid  = threadIdx.x;
    const int warp = tid >> 5;
    const int lane = tid & 31;

    float* ww_s = sm + 32 * OSTRIDE + warp * WARP_SM; // [16][24]
    int*   nb_s = (int*)(ww_s + 384);                 // [16]

    // ---- stage weights: Wf[o][w*16+i], col 272.. holds weight_res ----
    for (int idx = tid; idx < W_ * 512; idx += 128) {
        int w   = idx >> 9;
        int rem = idx & 511;
        int o   = rem >> 4;
        int i   = rem & 15;
        Wf[o * OSTRIDE + w * 16 + i] = weights[idx];
    }
    for (int idx = tid; idx < 512; idx += 128) {
        int o = idx >> 4, i = idx & 15;
        Wf[o * OSTRIDE + 272 + i] = weight_res[idx];
    }

    const int p = blockIdx.x * 4 + warp;

    // ---- per-warp staging: neighbor ids, masked ww (parity-split layout) ----
    if (lane < 16) {
        nb_s[lane] = neighbor_id[p * M_ + lane];
        ww_s[lane * WWM + 12 + 8] = 0.0f;     // wp1 slot8 = 0 (residual slot)
    }
    __syncwarp();
    for (int idx = lane; idx < 272; idx += 32) {
        int m = idx / 17;
        int w = idx - m * 17;
        float v = w_weights[(size_t)p * 272 + idx];
        // slot: wp = w&1 ; s = w>>1  (w=16 -> wp0 s8)
        ww_s[m * WWM + (w & 1) * 12 + (w >> 1)] = (nb_s[m] == P_) ? 0.0f : v;
    }
    __syncthreads();

    // lane bits: bg = bit4 ; wp = bit3 ; ih (channel pair) = bits 0-2
    // XOR-permuted slot ownership: oL = (lane>>2)&3 (= wp*2 + h2), jL = lane&3.
    const int bg = (lane >> 4) & 1;
    const int wp = (lane >> 3) & 1;
    const int ih = lane & 7;
    const int oL = (lane >> 2) & 3;
    const int jL = lane & 3;

    // physical batch slot sj holds batch b = bg + 2*(sj ^ jL)
    const float* xb[4];
    #pragma unroll
    for (int sj = 0; sj < 4; sj++)
        xb[sj] = in_pc + (size_t)(bg + 2 * (sj ^ jL)) * P_ * CI_ + 2 * ih;

    // gacc2[s][sj]: packed ch-pair accumulators. s=0..7: w=2s+wp ;
    // s=8: wp0 -> w=16 conv ; wp1 -> own-x (residual input, preserved by ww=0)
    ull gacc2[9][4];
    #pragma unroll
    for (int s = 0; s < 9; s++) {
        gacc2[s][0] = 0ull; gacc2[s][1] = 0ull;
        gacc2[s][2] = 0ull; gacc2[s][3] = 0ull;
    }
    if (wp) {
        size_t po = (size_t)p * CI_;
        #pragma unroll
        for (int sj = 0; sj < 4; sj++)
            gacc2[8][sj] = *(const ull*)(xb[sj] + po);
    }

    // ---- stage A ----
    const float* wwp = ww_s + wp * 12;
    #pragma unroll 4
    for (int m = 0; m < M_; m++) {
        int nb  = nb_s[m];
        int nbc = (nb == P_) ? 0 : nb;          // ww zeroed for pad
        size_t xo = (size_t)nbc * CI_;
        ull x0 = *(const ull*)(xb[0] + xo);
        ull x1 = *(const ull*)(xb[1] + xo);
        ull x2 = *(const ull*)(xb[2] + xo);
        ull x3 = *(const ull*)(xb[3] + xo);
        const float* wm = wwp + m * WWM;
        float4 fA = *(const float4*)(wm);
        float4 fB = *(const float4*)(wm + 4);
        float  f8 = wm[8];
        float fs[9] = {fA.x, fA.y, fA.z, fA.w, fB.x, fB.y, fB.z, fB.w, f8};
        #pragma unroll
        for (int s = 0; s < 9; s++) {
            ull f2;
            uint32_t fb = __float_as_uint(fs[s]);
            PACK_REPL_F32X2(f2, fb);
            FMA_F32X2(gacc2[s][0], f2, x0, gacc2[s][0]);
            FMA_F32X2(gacc2[s][1], f2, x1, gacc2[s][1]);
            FMA_F32X2(gacc2[s][2], f2, x2, gacc2[s][2]);
            FMA_F32X2(gacc2[s][3], f2, x3, gacc2[s][3]);
        }
    }

    // ---- stage B: XOR-permuted slots; each Wf LDS.64 feeds 4 FFMA2 ----
    // base includes this lane's w-parity and channel-pair offsets
    const float* wfb = Wf + wp * 16 + 2 * ih;
    const float* biasp = bias + (size_t)p * CO_;
    float* outb = out + ((size_t)(bg + 2 * jL) * P_ + p) * CO_;

    #pragma unroll 1
    for (int og = 0; og < 8; og++) {
        float av[4][4], rv[4][4];

        #pragma unroll
        for (int so = 0; so < 4; so++) {
            const float* wfoo = wfb + (size_t)(og * 4 + (so ^ oL)) * OSTRIDE;

            ull acc2[4] = {0ull, 0ull, 0ull, 0ull};
            #pragma unroll
            for (int s = 0; s < 8; s++) {
                ull wv = *(const ull*)(wfoo + s * 32);
                FMA_F32X2(acc2[0], wv, gacc2[s][0], acc2[0]);
                FMA_F32X2(acc2[1], wv, gacc2[s][1], acc2[1]);
                FMA_F32X2(acc2[2], wv, gacc2[s][2], acc2[2]);
                FMA_F32X2(acc2[3], wv, gacc2[s][3], acc2[3]);
            }
            // slot 8: wp0 -> conv w=16 ; wp1 -> residual weights
            ull wv8 = *(const ull*)(wfoo + 256);
            ull rt2[4] = {0ull, 0ull, 0ull, 0ull};
            if (wp == 0) {
                FMA_F32X2(acc2[0], wv8, gacc2[8][0], acc2[0]);
                FMA_F32X2(acc2[1], wv8, gacc2[8][1], acc2[1]);
                FMA_F32X2(acc2[2], wv8, gacc2[8][2], acc2[2]);
                FMA_F32X2(acc2[3], wv8, gacc2[8][3], acc2[3]);
            } else {
                MUL_F32X2(rt2[0], wv8, gacc2[8][0]);
                MUL_F32X2(rt2[1], wv8, gacc2[8][1]);
                MUL_F32X2(rt2[2], wv8, gacc2[8][2]);
                MUL_F32X2(rt2[3], wv8, gacc2[8][3]);
            }
            #pragma unroll
            for (int sj = 0; sj < 4; sj++) {
                uint32_t lo, hi;
                UNPACK_F32X2(lo, hi, acc2[sj]);
                av[so][sj] = __uint_as_float(lo) + __uint_as_float(hi);
                UNPACK_F32X2(lo, hi, rt2[sj]);
                rv[so][sj] = __uint_as_float(lo) + __uint_as_float(hi);
            }
        }

        // ---- select-free reduce-scatter (recursive halving, XOR slots) ----
        // lane-bit <-> slot-bit pairing: wp(8)<->so.1, h2(4)<->so.0,
        //                                h1(2)<->sj.1, h0(1)<->sj.0
        #pragma unroll
        for (int so = 0; so < 2; so++) {
            #pragma unroll
            for (int sj = 0; sj < 4; sj++) {
                av[so][sj] += __shfl_xor_sync(0xffffffffu, av[so + 2][sj], 8);
                rv[so][sj] += __shfl_xor_sync(0xffffffffu, rv[so + 2][sj], 8);
            }
        }
        #pragma unroll
        for (int sj = 0; sj < 4; sj++) {
            av[0][sj] += __shfl_xor_sync(0xffffffffu, av[1][sj], 4);
            rv[0][sj] += __shfl_xor_sync(0xffffffffu, rv[1][sj], 4);
        }
        #pragma unroll
        for (int sj = 0; sj < 2; sj++) {
            av[0][sj] += __shfl_xor_sync(0xffffffffu, av[0][sj + 2], 2);
            rv[0][sj] += __shfl_xor_sync(0xffffffffu, rv[0][sj + 2], 2);
        }
        av[0][0] += __shfl_xor_sync(0xffffffffu, av[0][1], 1);
        rv[0][0] += __shfl_xor_sync(0xffffffffu, rv[0][1], 1);

        // ---- epilogue: lane owns (o = og*4 + oL, b = bg + 2*jL) ----
        const int o = og * 4 + oL;
        float c = av[0][0] + biasp[o];
        float e = (c > 0.0f) ? c : expm1f(c);
        outb[o] = e * SQ_CONV + rv[0][0] * SQ_RES;
    }
}

extern "C" void kernel_launch(void* const* d_in, const int* in_sizes, int n_in,
                              void* d_out, int out_size)
{
    const float* in_pc       = nullptr;
    const float* weights     = nullptr;
    const float* bias        = nullptr;
    const float* w_weights   = nullptr;
    const float* weight_res  = nullptr;
    const int*   neighbor_id = nullptr;

    for (int i = 0; i < n_in; i++) {
        switch (in_sizes[i]) {
            case 2097152: in_pc       = (const float*)d_in[i]; break; // (8,16384,16)
            case 8704:    weights     = (const float*)d_in[i]; break; // (17,512)
            case 524288:  bias        = (const float*)d_in[i]; break; // (16384,32)
            case 4456448: w_weights   = (const float*)d_in[i]; break; // (16384,16,17)
            case 512:     weight_res  = (const float*)d_in[i]; break; // (32,16)
            case 262144:  neighbor_id = (const int*)d_in[i];   break; // (16384,16)
            default: break;
        }
    }

    const int smem_bytes = (32 * OSTRIDE + 4 * WARP_SM) * 4; // 43264
    cudaFuncSetAttribute(fused_conv_kernel,
                         cudaFuncAttributeMaxDynamicSharedMemorySize, smem_bytes);

    fused_conv_kernel<<<P_ / 4, 128, smem_bytes>>>(
        in_pc, weights, bias, w_weights, weight_res, neighbor_id, (float*)d_out);
}

// round 11
// speedup vs baseline: 1.0637x; 1.0130x over previous
#include <cuda_runtime.h>
#include <math.h>
#include <stdint.h>

// Problem constants
#define B_   8
#define P_   16384
#define M_   16
#define CI_  16
#define CO_  32
#define W_   17
#define OSTRIDE 288       // floats per output row in Wf (17 w-slots + residual col)
#define WWM  24           // per-m stride in ww_s (2 wp-halves of 12)
#define WARP_SM 400       // per-warp smem floats: ww 16*24=384 + nb 16

typedef unsigned long long ull;

// packed f32x2 (SASS FFMA2) — only reachable via PTX
#define FMA_F32X2(d, a, b, c) \
    asm("fma.rn.f32x2 %0, %1, %2, %3;" : "=l"(d) : "l"(a), "l"(b), "l"(c))
#define PACK_REPL_F32X2(out, s) \
    asm("mov.b64 %0, {%1, %1};" : "=l"(out) : "r"(s))
#define UNPACK_F32X2(lo, hi, in) \
    asm("mov.b64 {%0, %1}, %2;" : "=r"(lo), "=r"(hi) : "l"(in))

// smem (floats): Wf [32][288] = 9216 ; per-warp (4): ww[16][24] + nb[16] = 400
// total = 9216 + 1600 = 10816 floats = 43264 bytes

__global__ void __launch_bounds__(128, 4)
fused_conv_kernel(const float* __restrict__ in_pc,
                  const float* __restrict__ weights,
                  const float* __restrict__ bias,
                  const float* __restrict__ w_weights,
                  const int*   __restrict__ neighbor_id,
                  float*       __restrict__ out)
{
    constexpr float SQ_CONV = 0.70710678118654752440f;

    extern __shared__ float sm[];
    float* Wf = sm;                                   // [32][288]

    const int tid  = threadIdx.x;
    const int warp = tid >> 5;
    const int lane = tid & 31;

    float* ww_s = sm + 32 * OSTRIDE + warp * WARP_SM; // [16][24]
    int*   nb_s = (int*)(ww_s + 384);                 // [16]

    // ---- stage weights: Wf[o][w*16+i] (col 272.. unused this kernel) ----
    for (int idx = tid; idx < W_ * 512; idx += 128) {
        int w   = idx >> 9;
        int rem = idx & 511;
        int o   = rem >> 4;
        int i   = rem & 15;
        Wf[o * OSTRIDE + w * 16 + i] = weights[idx];
    }
    // zero the residual column so wp1's wv8 read is harmless AND defined
    for (int idx = tid; idx < 512; idx += 128) {
        int o = idx >> 4, i = idx & 15;
        Wf[o * OSTRIDE + 272 + i] = 0.0f;
    }

    const int p = blockIdx.x * 4 + warp;

    // ---- per-warp staging: neighbor ids, masked ww (parity-split layout) ----
    if (lane < 16) {
        nb_s[lane] = neighbor_id[p * M_ + lane];
        ww_s[lane * WWM + 12 + 8] = 0.0f;     // wp1 slot8 = 0 (unused slot)
    }
    __syncwarp();
    for (int idx = lane; idx < 272; idx += 32) {
        int m = idx / 17;
        int w = idx - m * 17;
        float v = w_weights[(size_t)p * 272 + idx];
        // slot: wp = w&1 ; s = w>>1  (w=16 -> wp0 s8)
        ww_s[m * WWM + (w & 1) * 12 + (w >> 1)] = (nb_s[m] == P_) ? 0.0f : v;
    }
    __syncthreads();

    // lane bits: bg = bit4 ; wp = bit3 ; ih (channel pair) = bits 0-2
    // XOR-permuted slot ownership: oL = (lane>>2)&3 (= wp*2 + h2), jL = lane&3.
    const int bg = (lane >> 4) & 1;
    const int wp = (lane >> 3) & 1;
    const int ih = lane & 7;
    const int oL = (lane >> 2) & 3;
    const int jL = lane & 3;

    // physical batch slot sj holds batch b = bg + 2*(sj ^ jL)
    const float* xb[4];
    #pragma unroll
    for (int sj = 0; sj < 4; sj++)
        xb[sj] = in_pc + (size_t)(bg + 2 * (sj ^ jL)) * P_ * CI_ + 2 * ih;

    // gacc2[s][sj]: packed ch-pair accumulators. s=0..7: w=2s+wp ;
    // s=8: wp0 -> w=16 conv ; wp1 -> zero (ww slot8 = 0)
    ull gacc2[9][4];
    #pragma unroll
    for (int s = 0; s < 9; s++) {
        gacc2[s][0] = 0ull; gacc2[s][1] = 0ull;
        gacc2[s][2] = 0ull; gacc2[s][3] = 0ull;
    }

    // ---- stage A ----
    const float* wwp = ww_s + wp * 12;
    #pragma unroll 4
    for (int m = 0; m < M_; m++) {
        int nb  = nb_s[m];
        int nbc = (nb == P_) ? 0 : nb;          // ww zeroed for pad
        size_t xo = (size_t)nbc * CI_;
        ull x0 = *(const ull*)(xb[0] + xo);
        ull x1 = *(const ull*)(xb[1] + xo);
        ull x2 = *(const ull*)(xb[2] + xo);
        ull x3 = *(const ull*)(xb[3] + xo);
        const float* wm = wwp + m * WWM;
        float4 fA = *(const float4*)(wm);
        float4 fB = *(const float4*)(wm + 4);
        float  f8 = wm[8];
        float fs[9] = {fA.x, fA.y, fA.z, fA.w, fB.x, fB.y, fB.z, fB.w, f8};
        #pragma unroll
        for (int s = 0; s < 9; s++) {
            ull f2;
            uint32_t fb = __float_as_uint(fs[s]);
            PACK_REPL_F32X2(f2, fb);
            FMA_F32X2(gacc2[s][0], f2, x0, gacc2[s][0]);
            FMA_F32X2(gacc2[s][1], f2, x1, gacc2[s][1]);
            FMA_F32X2(gacc2[s][2], f2, x2, gacc2[s][2]);
            FMA_F32X2(gacc2[s][3], f2, x3, gacc2[s][3]);
        }
    }

    // ---- stage B: XOR-permuted slots; each Wf LDS.64 feeds 4 FFMA2 ----
    const float* wfb = Wf + wp * 16 + 2 * ih;
    const float* biasp = bias + (size_t)p * CO_;
    float* outb = out + ((size_t)(bg + 2 * jL) * P_ + p) * CO_;

    #pragma unroll 2
    for (int og = 0; og < 8; og++) {
        float av[4][4];

        #pragma unroll
        for (int so = 0; so < 4; so++) {
            const float* wfoo = wfb + (size_t)(og * 4 + (so ^ oL)) * OSTRIDE;

            ull acc2[4] = {0ull, 0ull, 0ull, 0ull};
            #pragma unroll
            for (int s = 0; s < 8; s++) {
                ull wv = *(const ull*)(wfoo + s * 32);
                FMA_F32X2(acc2[0], wv, gacc2[s][0], acc2[0]);
                FMA_F32X2(acc2[1], wv, gacc2[s][1], acc2[1]);
                FMA_F32X2(acc2[2], wv, gacc2[s][2], acc2[2]);
                FMA_F32X2(acc2[3], wv, gacc2[s][3], acc2[3]);
            }
            // slot 8: wp0 -> conv w=16 (off 256) ; wp1 -> zero col (off 272) * 0
            ull wv8 = *(const ull*)(wfoo + 256);
            FMA_F32X2(acc2[0], wv8, gacc2[8][0], acc2[0]);
            FMA_F32X2(acc2[1], wv8, gacc2[8][1], acc2[1]);
            FMA_F32X2(acc2[2], wv8, gacc2[8][2], acc2[2]);
            FMA_F32X2(acc2[3], wv8, gacc2[8][3], acc2[3]);

            #pragma unroll
            for (int sj = 0; sj < 4; sj++) {
                uint32_t lo, hi;
                UNPACK_F32X2(lo, hi, acc2[sj]);
                av[so][sj] = __uint_as_float(lo) + __uint_as_float(hi);
            }
        }

        // ---- select-free reduce-scatter (recursive halving, XOR slots) ----
        #pragma unroll
        for (int so = 0; so < 2; so++) {
            #pragma unroll
            for (int sj = 0; sj < 4; sj++)
                av[so][sj] += __shfl_xor_sync(0xffffffffu, av[so + 2][sj], 8);
        }
        #pragma unroll
        for (int sj = 0; sj < 4; sj++)
            av[0][sj] += __shfl_xor_sync(0xffffffffu, av[1][sj], 4);
        #pragma unroll
        for (int sj = 0; sj < 2; sj++)
            av[0][sj] += __shfl_xor_sync(0xffffffffu, av[0][sj + 2], 2);
        av[0][0] += __shfl_xor_sync(0xffffffffu, av[0][1], 1);

        // ---- epilogue: lane owns (o = og*4 + oL, b = bg + 2*jL) ----
        const int o = og * 4 + oL;
        float c = av[0][0] + biasp[o];
        float e = (c > 0.0f) ? c : expm1f(c);
        outb[o] = e * SQ_CONV;            // residual added by kernel 2
    }
}

// ---- kernel 2: out += SQ_RES * (wres[o,:] . x[b,p,:]) ----
// warp handles 16 points, lane = o. wres row in registers; x via uniform ldg.
__global__ void __launch_bounds__(128, 8)
residual_kernel(const float* __restrict__ in_pc,
                const float* __restrict__ weight_res,
                float*       __restrict__ out)
{
    constexpr float SQ_RES = 0.70710678118654752440f;

    const int lane = threadIdx.x & 31;
    const int gw   = blockIdx.x * 4 + (threadIdx.x >> 5);

    float wr[16];
    #pragma unroll
    for (int c = 0; c < 4; c++) {
        float4 v = *(const float4*)&weight_res[lane * 16 + c * 4];
        wr[c*4+0] = v.x; wr[c*4+1] = v.y; wr[c*4+2] = v.z; wr[c*4+3] = v.w;
    }

    const int base = gw * 16;   // 16 (b,p) points per warp; B_*P_ = 131072 total
    #pragma unroll 4
    for (int t = 0; t < 16; t++) {
        const int pp = base + t;
        const float* xp = in_pc + (size_t)pp * CI_;
        float4 x0 = __ldg((const float4*)(xp));
        float4 x1 = __ldg((const float4*)(xp + 4));
        float4 x2 = __ldg((const float4*)(xp + 8));
        float4 x3 = __ldg((const float4*)(xp + 12));
        float r = wr[0]*x0.x + wr[1]*x0.y + wr[2]*x0.z + wr[3]*x0.w
                + wr[4]*x1.x + wr[5]*x1.y + wr[6]*x1.z + wr[7]*x1.w
                + wr[8]*x2.x + wr[9]*x2.y + wr[10]*x2.z + wr[11]*x2.w
                + wr[12]*x3.x + wr[13]*x3.y + wr[14]*x3.z + wr[15]*x3.w;
        float* op = out + (size_t)pp * CO_ + lane;
        *op += r * SQ_RES;
    }
}

extern "C" void kernel_launch(void* const* d_in, const int* in_sizes, int n_in,
                              void* d_out, int out_size)
{
    const float* in_pc       = nullptr;
    const float* weights     = nullptr;
    const float* bias        = nullptr;
    const float* w_weights   = nullptr;
    const float* weight_res  = nullptr;
    const int*   neighbor_id = nullptr;

    for (int i = 0; i < n_in; i++) {
        switch (in_sizes[i]) {
            case 2097152: in_pc       = (const float*)d_in[i]; break; // (8,16384,16)
            case 8704:    weights     = (const float*)d_in[i]; break; // (17,512)
            case 524288:  bias        = (const float*)d_in[i]; break; // (16384,32)
            case 4456448: w_weights   = (const float*)d_in[i]; break; // (16384,16,17)
            case 512:     weight_res  = (const float*)d_in[i]; break; // (32,16)
            case 262144:  neighbor_id = (const int*)d_in[i];   break; // (16384,16)
            default: break;
        }
    }

    const int smem_bytes = (32 * OSTRIDE + 4 * WARP_SM) * 4; // 43264
    cudaFuncSetAttribute(fused_conv_kernel,
                         cudaFuncAttributeMaxDynamicSharedMemorySize, smem_bytes);

    fused_conv_kernel<<<P_ / 4, 128, smem_bytes>>>(
        in_pc, weights, bias, w_weights, neighbor_id, (float*)d_out);

    // (B_*P_) points / 16 per warp / 4 warps per block = 2048 blocks
    residual_kernel<<<2048, 128>>>(in_pc, weight_res, (float*)d_out);
}